// round 13
// baseline (speedup 1.0000x reference)
#include <cuda_runtime.h>
#include <cuda_bf16.h>
#include <stdint.h>
#include <math.h>

// ---------------- problem constants ----------------
#define BSZ   1024
#define NSV   21
#define LROWS (BSZ*NSV)      // 21504
#define HDIM  256
#define PHN   25
#define ENCT  25
#define K2    272            // 256 (h) + 16 (inp); 17 chunks of 16
#define G4    1024           // 4*H gate width
#define OFS   (BSZ*PHN*NSV*4)

// ---------------- scratch (static device globals) ----------------
__device__ float g_h   [LROWS*HDIM];
__device__ float g_c   [LROWS*HDIM];
__device__ float g_inp [LROWS*16];
__device__ float g_kh  [LROWS*ENCT*8];
__device__ float g_vh  [LROWS*ENCT*8];
__device__ float g_y12 [LROWS*128];
__device__ float g_xi  [LROWS*8];
__device__ float g_loc [LROWS*4];
__device__ float g_eg  [LROWS*64];
__device__ float g_blr [G4];
__device__ float g_Geff[NSV*NSV];
__device__ float g_bfc [128];
__device__ float g_Whc [64*512];
__device__ float g_bhc [512];

// bf16 split operands
__device__ __align__(16) __nv_bfloat16 g_Ahi [LROWS*K2];
__device__ __align__(16) __nv_bfloat16 g_Alo [LROWS*K2];
__device__ __align__(16) __nv_bfloat16 g_Yhi [LROWS*HDIM];
__device__ __align__(16) __nv_bfloat16 g_Ylo [LROWS*HDIM];
__device__ __align__(16) __nv_bfloat16 g_WtLhi[G4*K2];
__device__ __align__(16) __nv_bfloat16 g_WtLlo[G4*K2];
__device__ __align__(16) __nv_bfloat16 g_WtFhi[128*HDIM];
__device__ __align__(16) __nv_bfloat16 g_WtFlo[128*HDIM];

__device__ __forceinline__ float sigm(float x) { return 1.0f / (1.0f + __expf(-x)); }

__device__ __forceinline__ float wredsum(float v) {
    #pragma unroll
    for (int o = 16; o; o >>= 1) v += __shfl_xor_sync(0xffffffffu, v, o);
    return v;
}
__device__ __forceinline__ float wredmax(float v) {
    #pragma unroll
    for (int o = 16; o; o >>= 1) v = fmaxf(v, __shfl_xor_sync(0xffffffffu, v, o));
    return v;
}
__device__ __forceinline__ void bf16_split(float s, __nv_bfloat16& hi, __nv_bfloat16& lo) {
    hi = __float2bfloat16(s);
    lo = __float2bfloat16(s - __bfloat162float(hi));
}

// ---------------- mma helpers ----------------
#define CP16(d, s)  asm volatile("cp.async.cg.shared.global [%0], [%1], 16;\n" :: "r"(d), "l"(s))
#define CPCOMMIT()  asm volatile("cp.async.commit_group;\n" ::)
#define CPWAIT(n)   asm volatile("cp.async.wait_group %0;\n" :: "n"(n))

__device__ __forceinline__ uint32_t lds_u32(uint32_t addr) {
    uint32_t v; asm volatile("ld.shared.b32 %0, [%1];" : "=r"(v) : "r"(addr)); return v;
}
__device__ __forceinline__ void mma_bf16(float* d, const uint32_t* a, const uint32_t* b) {
    asm volatile("mma.sync.aligned.m16n8k16.row.col.f32.bf16.bf16.f32 "
        "{%0,%1,%2,%3},{%4,%5,%6,%7},{%8,%9},{%0,%1,%2,%3};"
        : "+f"(d[0]), "+f"(d[1]), "+f"(d[2]), "+f"(d[3])
        : "r"(a[0]), "r"(a[1]), "r"(a[2]), "r"(a[3]), "r"(b[0]), "r"(b[1]));
}

// Double-buffered bf16x2 mma pipeline, 256 threads, warp tile 64x32.
// smem layout identical to the R6-proven one: sections 0:Ahi 1:Alo 2:Bhi 3:Blo,
// each [2 bufs][128 rows * 48B]; section stride 12288B, buffer stride 6144B.
// 8 warps: grid 2(m) x 4(n); per chunk: one K16 slice, 3 passes
// (hi*hi, hi*lo, lo*hi with A reloaded). acc[4][4][4].
template<int KCH>
__device__ __forceinline__ void mma_pipe(uint32_t sbase,
    const char* baseAhi, const char* baseAlo,
    const char* baseBhi, const char* baseBlo,
    int kbytes, float acc[4][4][4])
{
    const int tid  = threadIdx.x;
    const int warp = tid >> 5, lane = tid & 31;
    const int wm = warp >> 2, wn = warp & 3, g = lane >> 2, t4 = lane & 3;

    { // stage 0: 512 (sec,row) pairs over 256 threads
        #pragma unroll
        for (int p = 0; p < 2; p++) {
            int pi = tid + p*256;
            int sec = pi >> 7, r = pi & 127;
            const char* src = (sec == 0 ? baseAhi : sec == 1 ? baseAlo :
                               sec == 2 ? baseBhi : baseBlo) + (size_t)r * kbytes;
            uint32_t dst = sbase + (uint32_t)sec * 12288u + (uint32_t)r * 48u;
            CP16(dst, src); CP16(dst + 16, src + 16);
        }
        CPCOMMIT();
    }
    #pragma unroll 1
    for (int kc = 0; kc < KCH; kc++) {
        int buf = kc & 1;
        if (kc + 1 < KCH) {
            #pragma unroll
            for (int p = 0; p < 2; p++) {
                int pi = tid + p*256;
                int sec = pi >> 7, r = pi & 127;
                const char* src = (sec == 0 ? baseAhi : sec == 1 ? baseAlo :
                                   sec == 2 ? baseBhi : baseBlo)
                                  + (size_t)r * kbytes + (size_t)(kc + 1) * 32;
                uint32_t dst = sbase + (uint32_t)sec * 12288u
                             + (uint32_t)((kc + 1) & 1) * 6144u + (uint32_t)r * 48u;
                CP16(dst, src); CP16(dst + 16, src + 16);
            }
            CPCOMMIT();
            CPWAIT(1);
        } else {
            CPWAIT(0);
        }
        __syncthreads();

        uint32_t Ah[4][4], B0[4][2], B1[4][2];
        uint32_t abase = sbase + (uint32_t)buf * 6144u;
        #pragma unroll
        for (int mi = 0; mi < 4; mi++) {
            uint32_t o = abase + (uint32_t)(wm*64 + mi*16 + g) * 48u + t4*4u;
            Ah[mi][0] = lds_u32(o);       Ah[mi][1] = lds_u32(o + 384);
            Ah[mi][2] = lds_u32(o + 16);  Ah[mi][3] = lds_u32(o + 400);
        }
        uint32_t bbase = sbase + 24576u + (uint32_t)buf * 6144u;
        #pragma unroll
        for (int ni = 0; ni < 4; ni++) {
            uint32_t o = bbase + (uint32_t)(wn*32 + ni*8 + g) * 48u + t4*4u;
            B0[ni][0] = lds_u32(o);          B0[ni][1] = lds_u32(o + 16);
            B1[ni][0] = lds_u32(o + 12288);  B1[ni][1] = lds_u32(o + 12288 + 16);
        }
        // pass 1: Ahi * Bhi
        #pragma unroll
        for (int mi = 0; mi < 4; mi++)
            #pragma unroll
            for (int ni = 0; ni < 4; ni++) mma_bf16(acc[mi][ni], Ah[mi], B0[ni]);
        // pass 2: Ahi * Blo
        #pragma unroll
        for (int mi = 0; mi < 4; mi++)
            #pragma unroll
            for (int ni = 0; ni < 4; ni++) mma_bf16(acc[mi][ni], Ah[mi], B1[ni]);
        // pass 3: Alo * Bhi (reload A from lo section)
        #pragma unroll
        for (int mi = 0; mi < 4; mi++) {
            uint32_t o = abase + 12288u + (uint32_t)(wm*64 + mi*16 + g) * 48u + t4*4u;
            Ah[mi][0] = lds_u32(o);       Ah[mi][1] = lds_u32(o + 384);
            Ah[mi][2] = lds_u32(o + 16);  Ah[mi][3] = lds_u32(o + 400);
        }
        #pragma unroll
        for (int mi = 0; mi < 4; mi++)
            #pragma unroll
            for (int ni = 0; ni < 4; ni++) mma_bf16(acc[mi][ni], Ah[mi], B0[ni]);
        __syncthreads();
    }
}

// ---------------- prep (single launch): weights + kv + state ----------
__global__ void prep_all(const float* __restrict__ W_hh, const float* __restrict__ W_ih,
                         const float* __restrict__ b_lstm,
                         const float* __restrict__ G, const float* __restrict__ G_add,
                         const float* __restrict__ W_fc,  const float* __restrict__ b_fc,
                         const float* __restrict__ W_fc2, const float* __restrict__ b_fc2,
                         const float* __restrict__ W_h1,  const float* __restrict__ W_h2,
                         const float* __restrict__ b_h1,  const float* __restrict__ b_h2,
                         const float* __restrict__ fe,
                         const float* __restrict__ Wk, const float* __restrict__ bk,
                         const float* __restrict__ Wv, const float* __restrict__ bv,
                         const float* __restrict__ x) {
    int idx = blockIdx.x * blockDim.x + threadIdx.x;
    int stride = gridDim.x * blockDim.x;
    for (int i = idx; i < G4*K2; i += stride) {
        int n = i / K2, k = i - n*K2;
        int u = n >> 2, gate = n & 3;
        int oc = gate*256 + u;
        float w = (k < 256) ? W_hh[k*G4 + oc] : W_ih[(k-256)*G4 + oc];
        __nv_bfloat16 hi, lo; bf16_split(w, hi, lo);
        g_WtLhi[i] = hi; g_WtLlo[i] = lo;
    }
    for (int i = idx; i < G4; i += stride) {
        int u = i >> 2, gate = i & 3;
        g_blr[i] = b_lstm[gate*256 + u];
    }
    for (int i = idx; i < NSV*NSV; i += stride) g_Geff[i] = G[i] + G_add[i];
    for (int i = idx; i < 128*HDIM; i += stride) {
        int n = i >> 8, k = i & 255;
        float w = (n < 64) ? W_fc[k*64 + n] : W_fc2[k*64 + (n-64)];
        __nv_bfloat16 hi, lo; bf16_split(w, hi, lo);
        g_WtFhi[i] = hi; g_WtFlo[i] = lo;
    }
    for (int i = idx; i < 128; i += stride) g_bfc[i] = (i < 64) ? b_fc[i] : b_fc2[i-64];
    for (int i = idx; i < 64*512; i += stride) {
        int k = i >> 9, j = i & 511;
        g_Whc[i] = (j < 256) ? W_h1[k*256 + j] : W_h2[k*256 + (j-256)];
    }
    for (int i = idx; i < 512; i += stride) g_bhc[i] = (i < 256) ? b_h1[i] : b_h2[i-256];
    // kv
    for (int i = idx; i < LROWS*ENCT; i += stride) {
        int l = i / ENCT, t = i % ENCT;
        int b = l / NSV, n = l % NSV;
        const float* src = fe + (((b*ENCT) + t)*NSV + n)*8;
        float e[8];
        #pragma unroll
        for (int j = 0; j < 8; j++) e[j] = src[j];
        float* ko = g_kh + i*8;
        float* vo = g_vh + i*8;
        #pragma unroll
        for (int d = 0; d < 8; d++) {
            float sk = bk[d], sv = bv[d];
            #pragma unroll
            for (int j = 0; j < 8; j++) { sk += e[j]*Wk[j*8+d]; sv += e[j]*Wv[j*8+d]; }
            ko[d] = sk; vo[d] = sv;
        }
    }
    // xi0 / loc0
    for (int l = idx; l < LROWS; l += stride) {
        #pragma unroll
        for (int j = 0; j < 8; j++) g_xi[l*8+j] = x[l*8+j];
        #pragma unroll
        for (int c = 0; c < 4; c++) g_loc[l*4+c] = x[l*8+c];
    }
}

// ---------------- prep: mix enc_z with G -> g_eg (L x 64) --------------
__global__ void init_mix(const float* __restrict__ z, const float* __restrict__ enc,
                         const float* __restrict__ G) {
    __shared__ float sG[NSV*NSV];
    int b = blockIdx.x, i = threadIdx.x; // 64 threads
    for (int t = i; t < NSV*NSV; t += 64) sG[t] = G[t];
    __syncthreads();
    float v[NSV];
    if (i < 32) {
        #pragma unroll
        for (int m = 0; m < NSV; m++) v[m] = z[(b*NSV+m)*32 + i];
    } else {
        #pragma unroll
        for (int m = 0; m < NSV; m++) v[m] = enc[(b*NSV+m)*32 + (i-32)];
    }
    #pragma unroll
    for (int n = 0; n < NSV; n++) {
        float s = 0.f;
        #pragma unroll
        for (int m = 0; m < NSV; m++) s += sG[n*NSV+m]*v[m];
        g_eg[(b*NSV+n)*64 + i] = s;
    }
}

// ---------------- prep: h0/c0 = eg @ [W_h1|W_h2] + bias ----------------
__global__ void __launch_bounds__(256) init_gemm() {
    __shared__ float As[8][128];
    __shared__ float Bs[8][128];
    int tid = threadIdx.x;
    int bn = blockIdx.x, bm = blockIdx.y;
    int tx = tid & 15, ty = tid >> 4;
    float acc[8][8];
    #pragma unroll
    for (int i = 0; i < 8; i++)
        #pragma unroll
        for (int j = 0; j < 8; j++) acc[i][j] = 0.f;
    const float* A = g_eg + bm*128*64;
    int arow = tid >> 1, acol = (tid & 1)*4;
    int brow = tid >> 5, bcol = (tid & 31)*4;
    for (int k0 = 0; k0 < 64; k0 += 8) {
        float4 av = *(const float4*)(A + arow*64 + k0 + acol);
        As[acol+0][arow] = av.x; As[acol+1][arow] = av.y;
        As[acol+2][arow] = av.z; As[acol+3][arow] = av.w;
        float4 bv = *(const float4*)(g_Whc + (k0+brow)*512 + bn*128 + bcol);
        *(float4*)&Bs[brow][bcol] = bv;
        __syncthreads();
        #pragma unroll
        for (int kk = 0; kk < 8; kk++) {
            float a[8], bb[8];
            #pragma unroll
            for (int i = 0; i < 8; i++) a[i]  = As[kk][ty*8+i];
            #pragma unroll
            for (int j = 0; j < 8; j++) bb[j] = Bs[kk][tx*8+j];
            #pragma unroll
            for (int i = 0; i < 8; i++)
                #pragma unroll
                for (int j = 0; j < 8; j++) acc[i][j] += a[i]*bb[j];
        }
        __syncthreads();
    }
    #pragma unroll
    for (int i = 0; i < 8; i++) {
        int l = bm*128 + ty*8 + i;
        #pragma unroll
        for (int j = 0; j < 8; j++) {
            int col = bn*128 + tx*8 + j;
            float v = acc[i][j] + g_bhc[col];
            if (col < 256) g_h[l*HDIM + col] = v;
            else           g_c[l*HDIM + (col-256)] = v;
        }
    }
}

// ---------------- step: q + attention + inp build (warp per row) -------
__global__ void attn_kernel(const float* __restrict__ Whd, const float* __restrict__ bhd,
                            const float* __restrict__ Wq,  const float* __restrict__ bq,
                            const float* __restrict__ Wo,  const float* __restrict__ bo) {
    __shared__ float sWhd[HDIM*8];
    __shared__ float sWq[64], sWo[64], sbq[8], sbo[8], sbhd[8];
    int tid = threadIdx.x;
    for (int i = tid; i < HDIM*8; i += 256) sWhd[i] = Whd[i];
    if (tid < 64) { sWq[tid] = Wq[tid]; sWo[tid] = Wo[tid]; }
    if (tid < 8)  { sbq[tid] = bq[tid]; sbo[tid] = bo[tid]; sbhd[tid] = bhd[tid]; }
    __syncthreads();
    int w = tid >> 5, lane = tid & 31;
    int l = blockIdx.x*8 + w;
    const float* crow = g_c + l*HDIM;
    float qa[8];
    #pragma unroll
    for (int j = 0; j < 8; j++) qa[j] = 0.f;
    for (int kk = lane; kk < HDIM; kk += 32) {
        float cv = crow[kk];
        #pragma unroll
        for (int j = 0; j < 8; j++) qa[j] += cv * sWhd[kk*8+j];
    }
    #pragma unroll
    for (int j = 0; j < 8; j++) qa[j] = wredsum(qa[j]) + sbhd[j];
    float qh[8];
    #pragma unroll
    for (int j = 0; j < 8; j++) {
        float s = sbq[j];
        #pragma unroll
        for (int d = 0; d < 8; d++) s += qa[d]*sWq[d*8+j];
        qh[j] = s;
    }
    float l0 = -1e30f, l1 = -1e30f;
    if (lane < ENCT) {
        const float4* kp = (const float4*)(g_kh + (l*ENCT + lane)*8);
        float4 k0 = kp[0], k1 = kp[1];
        l0 = 0.5f*(qh[0]*k0.x + qh[1]*k0.y + qh[2]*k0.z + qh[3]*k0.w);
        l1 = 0.5f*(qh[4]*k1.x + qh[5]*k1.y + qh[6]*k1.z + qh[7]*k1.w);
    }
    float m0 = wredmax(l0), m1 = wredmax(l1);
    float e0 = (lane < ENCT) ? __expf(l0 - m0) : 0.f;
    float e1 = (lane < ENCT) ? __expf(l1 - m1) : 0.f;
    float s0 = wredsum(e0), s1 = wredsum(e1);
    float w0 = e0 / s0, w1 = e1 / s1;
    float od[8];
    #pragma unroll
    for (int j = 0; j < 8; j++) od[j] = 0.f;
    if (lane < ENCT) {
        const float4* vp = (const float4*)(g_vh + (l*ENCT + lane)*8);
        float4 v0 = vp[0], v1 = vp[1];
        od[0] = w0*v0.x; od[1] = w0*v0.y; od[2] = w0*v0.z; od[3] = w0*v0.w;
        od[4] = w1*v1.x; od[5] = w1*v1.y; od[6] = w1*v1.z; od[7] = w1*v1.w;
    }
    #pragma unroll
    for (int j = 0; j < 8; j++) od[j] = wredsum(od[j]);
    float aval = 0.f;
    #pragma unroll
    for (int j = 0; j < 8; j++) {
        if (lane == j) {
            float s = sbo[j];
            #pragma unroll
            for (int d = 0; d < 8; d++) s += od[d]*sWo[d*8+j];
            aval = qa[j] + s;
        }
    }
    if (lane < 8) {
        g_inp[l*16 + lane]     = g_xi[l*8 + lane];
        g_inp[l*16 + 8 + lane] = aval;
    }
}

// ---------------- step: Geff-mix of [h | inp] -> bf16 split A (L x 272)
__global__ void mix_hg_kernel() {
    __shared__ float sG[NSV*NSV];
    int b = blockIdx.x, k = threadIdx.x; // 272 threads
    for (int i = threadIdx.x; i < NSV*NSV; i += blockDim.x) sG[i] = g_Geff[i];
    __syncthreads();
    float v[NSV];
    if (k < 256) {
        #pragma unroll
        for (int m = 0; m < NSV; m++) v[m] = g_h[(b*NSV+m)*HDIM + k];
    } else {
        int kk = k - 256;
        #pragma unroll
        for (int m = 0; m < NSV; m++) v[m] = g_inp[(b*NSV+m)*16 + kk];
    }
    #pragma unroll
    for (int n = 0; n < NSV; n++) {
        float s = 0.f;
        #pragma unroll
        for (int m = 0; m < NSV; m++) s += sG[n*NSV+m]*v[m];
        __nv_bfloat16 hi, lo; bf16_split(s, hi, lo);
        int o = (b*NSV+n)*K2 + k;
        g_Ahi[o] = hi; g_Alo[o] = lo;
    }
}

// ---------------- step: big GEMM (L x 272 @ 272 x 1024) + LSTM cell ----
__global__ void __launch_bounds__(256, 2) lstm_mma() {
    __shared__ __align__(16) __nv_bfloat16 sm[8*128*24]; // 48KB
    float acc[4][4][4];
    #pragma unroll
    for (int i = 0; i < 4; i++)
        #pragma unroll
        for (int j = 0; j < 4; j++)
            #pragma unroll
            for (int kq = 0; kq < 4; kq++) acc[i][j][kq] = 0.f;
    int bn = blockIdx.x, bm = blockIdx.y;
    uint32_t sbase = (uint32_t)__cvta_generic_to_shared(sm);
    mma_pipe<17>(sbase,
        (const char*)g_Ahi  + (size_t)bm*128*544,
        (const char*)g_Alo  + (size_t)bm*128*544,
        (const char*)g_WtLhi + (size_t)bn*128*544,
        (const char*)g_WtLlo + (size_t)bn*128*544,
        544, acc);

    // fused LSTM epilogue (same gate-exchange as R6, per mi)
    const int tid = threadIdx.x;
    const int warp = tid >> 5, lane = tid & 31;
    const int wm = warp >> 2, wn = warp & 3, g = lane >> 2, t4 = lane & 3;
    const bool odd = (t4 & 1);
    #pragma unroll
    for (int mi = 0; mi < 4; mi++) {
        #pragma unroll
        for (int ni = 0; ni < 4; ni++) {
            int row = bm*128 + wm*64 + mi*16 + g;
            int cn  = bn*128 + wn*32 + ni*8 + t4*2;
            float b0 = g_blr[cn], b1 = g_blr[cn+1];
            float s0 = acc[mi][ni][0] + b0;
            float s1 = acc[mi][ni][1] + b1;
            float s2 = acc[mi][ni][2] + b0;
            float s3 = acc[mi][ni][3] + b1;
            float x0 = __shfl_xor_sync(0xffffffffu, odd ? s0 : s2, 1);
            float x1 = __shfl_xor_sync(0xffffffffu, odd ? s1 : s3, 1);
            int r  = row + (odd ? 8 : 0);
            float gi = odd ? x0 : s0;
            float gf = odd ? x1 : s1;
            float gg = odd ? s2 : x0;
            float go = odd ? s3 : x1;
            int u  = cn >> 2;
            int ci = r*HDIM + u;
            float cold = g_c[ci];
            float c2 = sigm(gf)*cold + sigm(gi)*tanhf(gg);
            float h2 = sigm(go)*tanhf(c2);
            g_c[ci] = c2;
            g_h[ci] = h2;
        }
    }
}

// ---------------- step: G-mix of relu(h2) -> bf16 split Y (L x 256) ----
__global__ void mix_yi(const float* __restrict__ G) {
    __shared__ float sG[NSV*NSV];
    int b = blockIdx.x, k = threadIdx.x; // 256 threads
    for (int i = threadIdx.x; i < NSV*NSV; i += blockDim.x) sG[i] = G[i];
    __syncthreads();
    float v[NSV];
    #pragma unroll
    for (int m = 0; m < NSV; m++) v[m] = fmaxf(g_h[(b*NSV+m)*HDIM + k], 0.f);
    #pragma unroll
    for (int n = 0; n < NSV; n++) {
        float s = 0.f;
        #pragma unroll
        for (int m = 0; m < NSV; m++) s += sG[n*NSV+m]*v[m];
        __nv_bfloat16 hi, lo; bf16_split(s, hi, lo);
        int o = (b*NSV+n)*HDIM + k;
        g_Yhi[o] = hi; g_Ylo[o] = lo;
    }
}

// ---------------- step: fc GEMM (L x 256 @ 256 x 128) + relu -----------
__global__ void __launch_bounds__(256, 2) fc_mma() {
    __shared__ __align__(16) __nv_bfloat16 sm[8*128*24]; // 48KB
    float acc[4][4][4];
    #pragma unroll
    for (int i = 0; i < 4; i++)
        #pragma unroll
        for (int j = 0; j < 4; j++)
            #pragma unroll
            for (int kq = 0; kq < 4; kq++) acc[i][j][kq] = 0.f;
    int bm = blockIdx.y;
    uint32_t sbase = (uint32_t)__cvta_generic_to_shared(sm);
    mma_pipe<16>(sbase,
        (const char*)g_Yhi + (size_t)bm*128*512,
        (const char*)g_Ylo + (size_t)bm*128*512,
        (const char*)g_WtFhi,
        (const char*)g_WtFlo,
        512, acc);

    const int tid = threadIdx.x;
    const int warp = tid >> 5, lane = tid & 31;
    const int wm = warp >> 2, wn = warp & 3, g = lane >> 2, t4 = lane & 3;
    #pragma unroll
    for (int mi = 0; mi < 4; mi++) {
        #pragma unroll
        for (int ni = 0; ni < 4; ni++) {
            int row = bm*128 + wm*64 + mi*16 + g;
            int col = wn*32 + ni*8 + t4*2;
            float b0 = g_bfc[col], b1 = g_bfc[col+1];
            g_y12[row*128 + col]       = fmaxf(acc[mi][ni][0] + b0, 0.f);
            g_y12[row*128 + col + 1]   = fmaxf(acc[mi][ni][1] + b1, 0.f);
            g_y12[(row+8)*128 + col]   = fmaxf(acc[mi][ni][2] + b0, 0.f);
            g_y12[(row+8)*128 + col+1] = fmaxf(acc[mi][ni][3] + b1, 0.f);
        }
    }
}

// ---------------- step: tail — per-batch block, y12 staged in smem -----
__global__ void __launch_bounds__(672) final_kernel(
    const float* __restrict__ G,
    const float* __restrict__ Wloc, const float* __restrict__ bloc,
    const float* __restrict__ Wlz,  const float* __restrict__ blz,
    float* __restrict__ out, int t) {
    __shared__ float sY[NSV][128];
    __shared__ float sG[NSV*NSV], sWl[64*3], sWz[64*4], sbl[3], sbz[4];
    int tid = threadIdx.x;
    int b = blockIdx.x;
    for (int i = tid; i < NSV*NSV; i += 672) sG[i] = G[i];
    if (tid < 64*3) sWl[tid] = Wloc[tid];
    if (tid < 64*4) sWz[tid] = Wlz[tid];
    if (tid < 3)    sbl[tid] = bloc[tid];
    if (tid < 4)    sbz[tid] = blz[tid];
    for (int i = tid; i < NSV*128; i += 672)
        sY[i >> 7][i & 127] = g_y12[b*NSV*128 + i];
    __syncthreads();
    int n = tid >> 5, lane = tid & 31;
    int l = b*NSV + n;
    float a0 = 0.f, a1 = 0.f, a2 = 0.f, a3 = 0.f;
    #pragma unroll
    for (int m = 0; m < NSV; m++) {
        float g = sG[n*NSV+m];
        a0 += g*sY[m][lane];      a1 += g*sY[m][lane+32];
        a2 += g*sY[m][lane+64];   a3 += g*sY[m][lane+96];
    }
    float p0 = a0*sWl[lane*3+0] + a1*sWl[(lane+32)*3+0];
    float p1 = a0*sWl[lane*3+1] + a1*sWl[(lane+32)*3+1];
    float p2 = a0*sWl[lane*3+2] + a1*sWl[(lane+32)*3+2];
    float z0 = a2*sWz[lane*4+0] + a3*sWz[(lane+32)*4+0];
    float z1 = a2*sWz[lane*4+1] + a3*sWz[(lane+32)*4+1];
    float z2 = a2*sWz[lane*4+2] + a3*sWz[(lane+32)*4+2];
    float z3 = a2*sWz[lane*4+3] + a3*sWz[(lane+32)*4+3];
    p0 = wredsum(p0) + sbl[0];
    p1 = wredsum(p1) + sbl[1];
    p2 = wredsum(p2) + sbl[2];
    z0 = (wredsum(z0) + sbz[0])*100.f;
    z1 = (wredsum(z1) + sbz[1])*100.f;
    z2 = (wredsum(z2) + sbz[2])*100.f;
    z3 = (wredsum(z3) + sbz[3])*100.f;
    float inv = rsqrtf(1.f + p0*p0 + p1*p1 + p2*p2);
    float qdw = inv, qdx = p0*inv, qdy = p1*inv, qdz = p2*inv;
    float4 qs = *(const float4*)(g_loc + l*4);
    float lw = qs.x*qdw - (qs.y*qdx + qs.z*qdy + qs.w*qdz);
    float vx = qs.x*qdx + qdw*qs.y + (qs.z*qdz - qs.w*qdy);
    float vy = qs.x*qdy + qdw*qs.z + (qs.w*qdx - qs.y*qdz);
    float vz = qs.x*qdz + qdw*qs.w + (qs.y*qdy - qs.z*qdx);
    if (lane == 0) {
        int base = ((b*PHN + t)*NSV + n)*4;
        out[base+0] = lw;  out[base+1] = vx;  out[base+2] = vy;  out[base+3] = vz;
        out[OFS + base+0] = qdw; out[OFS + base+1] = qdx;
        out[OFS + base+2] = qdy; out[OFS + base+3] = qdz;
        out[2*OFS + base+0] = z0; out[2*OFS + base+1] = z1;
        out[2*OFS + base+2] = z2; out[2*OFS + base+3] = z3;
        g_loc[l*4+0] = lw; g_loc[l*4+1] = vx; g_loc[l*4+2] = vy; g_loc[l*4+3] = vz;
        g_xi[l*8+0] = lw;  g_xi[l*8+1] = vx;  g_xi[l*8+2] = vy;  g_xi[l*8+3] = vz;
        g_xi[l*8+4] = qdw; g_xi[l*8+5] = qdx; g_xi[l*8+6] = qdy; g_xi[l*8+7] = qdz;
    }
}

// ---------------- launch ----------------
extern "C" void kernel_launch(void* const* d_in, const int* in_sizes, int n_in,
                              void* d_out, int out_size) {
    (void)in_sizes; (void)n_in; (void)out_size;
    const float* x      = (const float*)d_in[0];
    const float* enc    = (const float*)d_in[1];
    const float* fe     = (const float*)d_in[2];
    const float* z      = (const float*)d_in[3];
    const float* G      = (const float*)d_in[5];
    const float* G_add  = (const float*)d_in[6];
    const float* W_ih   = (const float*)d_in[7];
    const float* W_hh   = (const float*)d_in[8];
    const float* b_lstm = (const float*)d_in[9];
    const float* W_fc   = (const float*)d_in[10];
    const float* b_fc   = (const float*)d_in[11];
    const float* W_fc2  = (const float*)d_in[12];
    const float* b_fc2  = (const float*)d_in[13];
    const float* W_h1   = (const float*)d_in[14];
    const float* b_h1   = (const float*)d_in[15];
    const float* W_h2   = (const float*)d_in[16];
    const float* b_h2   = (const float*)d_in[17];
    const float* W_hd   = (const float*)d_in[18];
    const float* b_hd   = (const float*)d_in[19];
    const float* Wq     = (const float*)d_in[20];
    const float* bq     = (const float*)d_in[21];
    const float* Wk     = (const float*)d_in[22];
    const float* bk     = (const float*)d_in[23];
    const float* Wv     = (const float*)d_in[24];
    const float* bv     = (const float*)d_in[25];
    const float* Wo     = (const float*)d_in[26];
    const float* bo     = (const float*)d_in[27];
    const float* W_loc  = (const float*)d_in[28];
    const float* b_loc  = (const float*)d_in[29];
    const float* W_lz   = (const float*)d_in[30];
    const float* b_lz   = (const float*)d_in[31];
    float* out = (float*)d_out;

    prep_all<<<1024, 256>>>(W_hh, W_ih, b_lstm, G, G_add,
                            W_fc, b_fc, W_fc2, b_fc2, W_h1, W_h2, b_h1, b_h2,
                            fe, Wk, bk, Wv, bv, x);
    init_mix<<<BSZ, 64>>>(z, enc, G);
    init_gemm<<<dim3(4, 168), 256>>>();

    for (int t = 0; t < PHN; t++) {
        attn_kernel<<<LROWS/8, 256>>>(W_hd, b_hd, Wq, bq, Wo, bo);
        mix_hg_kernel<<<BSZ, 272>>>();
        lstm_mma<<<dim3(8, 168), 256>>>();
        mix_yi<<<BSZ, 256>>>(G);
        fc_mma<<<dim3(1, 168), 256>>>();
        final_kernel<<<BSZ, 672>>>(G, W_loc, b_loc, W_lz, b_lz, out, t);
    }
}

// round 16
// speedup vs baseline: 1.0647x; 1.0647x over previous
#include <cuda_runtime.h>
#include <cuda_bf16.h>
#include <stdint.h>
#include <math.h>

// ---------------- problem constants ----------------
#define BSZ   1024
#define NSV   21
#define LROWS (BSZ*NSV)      // 21504
#define HDIM  256
#define PHN   25
#define ENCT  25
#define K2    272            // 256 (h) + 16 (inp)
#define G4    1024           // 4*H gate width
#define OFS   (BSZ*PHN*NSV*4)

// ---------------- scratch (static device globals) ----------------
__device__ float g_h   [LROWS*HDIM];
__device__ float g_c   [LROWS*HDIM];
__device__ float g_inp [LROWS*16];
__device__ float g_kh  [LROWS*ENCT*8];
__device__ float g_vh  [LROWS*ENCT*8];
__device__ float g_y12 [LROWS*128];
__device__ float g_xi  [LROWS*8];
__device__ float g_loc [LROWS*4];
__device__ float g_eg  [LROWS*64];
__device__ float g_blr [G4];
__device__ float g_Geff[NSV*NSV];
__device__ float g_bfc [128];
__device__ float g_Whc [64*512];
__device__ float g_bhc [512];

// bf16 split operands
__device__ __align__(16) __nv_bfloat16 g_Ahi [LROWS*K2];
__device__ __align__(16) __nv_bfloat16 g_Alo [LROWS*K2];
__device__ __align__(16) __nv_bfloat16 g_Yhi [LROWS*HDIM];
__device__ __align__(16) __nv_bfloat16 g_Ylo [LROWS*HDIM];
__device__ __align__(16) __nv_bfloat16 g_WtLhi[G4*K2];
__device__ __align__(16) __nv_bfloat16 g_WtLlo[G4*K2];
__device__ __align__(16) __nv_bfloat16 g_WtFhi[128*HDIM];
__device__ __align__(16) __nv_bfloat16 g_WtFlo[128*HDIM];

__device__ __forceinline__ float sigm(float x) { return 1.0f / (1.0f + __expf(-x)); }

__device__ __forceinline__ float wredsum(float v) {
    #pragma unroll
    for (int o = 16; o; o >>= 1) v += __shfl_xor_sync(0xffffffffu, v, o);
    return v;
}
__device__ __forceinline__ float wredmax(float v) {
    #pragma unroll
    for (int o = 16; o; o >>= 1) v = fmaxf(v, __shfl_xor_sync(0xffffffffu, v, o));
    return v;
}
__device__ __forceinline__ void bf16_split(float s, __nv_bfloat16& hi, __nv_bfloat16& lo) {
    hi = __float2bfloat16(s);
    lo = __float2bfloat16(s - __bfloat162float(hi));
}

// ---------------- mma helpers ----------------
#define CP16(d, s)  asm volatile("cp.async.cg.shared.global [%0], [%1], 16;\n" :: "r"(d), "l"(s))
#define CPCOMMIT()  asm volatile("cp.async.commit_group;\n" ::)
#define CPWAIT(n)   asm volatile("cp.async.wait_group %0;\n" :: "n"(n))

__device__ __forceinline__ uint32_t lds_u32(uint32_t addr) {
    uint32_t v; asm volatile("ld.shared.b32 %0, [%1];" : "=r"(v) : "r"(addr)); return v;
}
__device__ __forceinline__ void mma_bf16(float* d, const uint32_t* a, const uint32_t* b) {
    asm volatile("mma.sync.aligned.m16n8k16.row.col.f32.bf16.bf16.f32 "
        "{%0,%1,%2,%3},{%4,%5,%6,%7},{%8,%9},{%0,%1,%2,%3};"
        : "+f"(d[0]), "+f"(d[1]), "+f"(d[2]), "+f"(d[3])
        : "r"(a[0]), "r"(a[1]), "r"(a[2]), "r"(a[3]), "r"(b[0]), "r"(b[1]));
}

// Double-buffered bf16x2 mma pipeline — the R6/R11-MEASURED configuration.
// 512 threads: warp grid 4(m)x4(n), warp tile 32x32 -> acc[2][4][4].
template<int KCH>
__device__ __forceinline__ void mma_pipe(uint32_t sbase,
    const char* baseAhi, const char* baseAlo,
    const char* baseBhi, const char* baseBlo,
    int kbytes, float acc[2][4][4])
{
    const int tid  = threadIdx.x;
    const int warp = tid >> 5, lane = tid & 31;
    const int wm = warp >> 2, wn = warp & 3, g = lane >> 2, t4 = lane & 3;
    const int sec = tid >> 7, r = tid & 127;
    const char* mysrc = (sec == 0 ? baseAhi : sec == 1 ? baseAlo : sec == 2 ? baseBhi : baseBlo)
                        + (size_t)r * kbytes;
    const uint32_t mydst = sbase + (uint32_t)sec * 12288u + (uint32_t)r * 48u;

    { // stage 0
        CP16(mydst, mysrc); CP16(mydst + 16, mysrc + 16);
        CPCOMMIT();
    }
    #pragma unroll 1
    for (int kc = 0; kc < KCH; kc++) {
        int buf = kc & 1;
        if (kc + 1 < KCH) {
            const char* s = mysrc + (size_t)(kc + 1) * 32;
            uint32_t d = mydst + (uint32_t)((kc + 1) & 1) * 6144u;
            CP16(d, s); CP16(d + 16, s + 16);
            CPCOMMIT();
            CPWAIT(1);
        } else {
            CPWAIT(0);
        }
        __syncthreads();

        uint32_t Ah[2][4], B0[4][2], B1[4][2];
        uint32_t abase = sbase + (uint32_t)buf * 6144u;
        #pragma unroll
        for (int mi = 0; mi < 2; mi++) {
            uint32_t o = abase + (uint32_t)(wm*32 + mi*16 + g) * 48u + t4*4u;
            Ah[mi][0] = lds_u32(o);       Ah[mi][1] = lds_u32(o + 384);
            Ah[mi][2] = lds_u32(o + 16);  Ah[mi][3] = lds_u32(o + 400);
        }
        uint32_t bbase = sbase + 24576u + (uint32_t)buf * 6144u;
        #pragma unroll
        for (int ni = 0; ni < 4; ni++) {
            uint32_t o = bbase + (uint32_t)(wn*32 + ni*8 + g) * 48u + t4*4u;
            B0[ni][0] = lds_u32(o);          B0[ni][1] = lds_u32(o + 16);
            B1[ni][0] = lds_u32(o + 12288);  B1[ni][1] = lds_u32(o + 12288 + 16);
        }
        // pass 1: Ahi * Bhi
        #pragma unroll
        for (int mi = 0; mi < 2; mi++)
            #pragma unroll
            for (int ni = 0; ni < 4; ni++) mma_bf16(acc[mi][ni], Ah[mi], B0[ni]);
        // pass 2: Ahi * Blo
        #pragma unroll
        for (int mi = 0; mi < 2; mi++)
            #pragma unroll
            for (int ni = 0; ni < 4; ni++) mma_bf16(acc[mi][ni], Ah[mi], B1[ni]);
        // pass 3: Alo * Bhi (reload A from lo section)
        #pragma unroll
        for (int mi = 0; mi < 2; mi++) {
            uint32_t o = abase + 12288u + (uint32_t)(wm*32 + mi*16 + g) * 48u + t4*4u;
            Ah[mi][0] = lds_u32(o);       Ah[mi][1] = lds_u32(o + 384);
            Ah[mi][2] = lds_u32(o + 16);  Ah[mi][3] = lds_u32(o + 400);
        }
        #pragma unroll
        for (int mi = 0; mi < 2; mi++)
            #pragma unroll
            for (int ni = 0; ni < 4; ni++) mma_bf16(acc[mi][ni], Ah[mi], B0[ni]);
        __syncthreads();
    }
}

// ---------------- prep (single launch): weights + kv + state ----------
__global__ void prep_all(const float* __restrict__ W_hh, const float* __restrict__ W_ih,
                         const float* __restrict__ b_lstm,
                         const float* __restrict__ G, const float* __restrict__ G_add,
                         const float* __restrict__ W_fc,  const float* __restrict__ b_fc,
                         const float* __restrict__ W_fc2, const float* __restrict__ b_fc2,
                         const float* __restrict__ W_h1,  const float* __restrict__ W_h2,
                         const float* __restrict__ b_h1,  const float* __restrict__ b_h2,
                         const float* __restrict__ fe,
                         const float* __restrict__ Wk, const float* __restrict__ bk,
                         const float* __restrict__ Wv, const float* __restrict__ bv,
                         const float* __restrict__ x) {
    int idx = blockIdx.x * blockDim.x + threadIdx.x;
    int stride = gridDim.x * blockDim.x;
    for (int i = idx; i < G4*K2; i += stride) {
        int n = i / K2, k = i - n*K2;
        int u = n >> 2, gate = n & 3;
        int oc = gate*256 + u;
        float w = (k < 256) ? W_hh[k*G4 + oc] : W_ih[(k-256)*G4 + oc];
        __nv_bfloat16 hi, lo; bf16_split(w, hi, lo);
        g_WtLhi[i] = hi; g_WtLlo[i] = lo;
    }
    for (int i = idx; i < G4; i += stride) {
        int u = i >> 2, gate = i & 3;
        g_blr[i] = b_lstm[gate*256 + u];
    }
    for (int i = idx; i < NSV*NSV; i += stride) g_Geff[i] = G[i] + G_add[i];
    for (int i = idx; i < 128*HDIM; i += stride) {
        int n = i >> 8, k = i & 255;
        float w = (n < 64) ? W_fc[k*64 + n] : W_fc2[k*64 + (n-64)];
        __nv_bfloat16 hi, lo; bf16_split(w, hi, lo);
        g_WtFhi[i] = hi; g_WtFlo[i] = lo;
    }
    for (int i = idx; i < 128; i += stride) g_bfc[i] = (i < 64) ? b_fc[i] : b_fc2[i-64];
    for (int i = idx; i < 64*512; i += stride) {
        int k = i >> 9, j = i & 511;
        g_Whc[i] = (j < 256) ? W_h1[k*256 + j] : W_h2[k*256 + (j-256)];
    }
    for (int i = idx; i < 512; i += stride) g_bhc[i] = (i < 256) ? b_h1[i] : b_h2[i-256];
    for (int i = idx; i < LROWS*ENCT; i += stride) {
        int l = i / ENCT, t = i % ENCT;
        int b = l / NSV, n = l % NSV;
        const float* src = fe + (((b*ENCT) + t)*NSV + n)*8;
        float e[8];
        #pragma unroll
        for (int j = 0; j < 8; j++) e[j] = src[j];
        float* ko = g_kh + i*8;
        float* vo = g_vh + i*8;
        #pragma unroll
        for (int d = 0; d < 8; d++) {
            float sk = bk[d], sv = bv[d];
            #pragma unroll
            for (int j = 0; j < 8; j++) { sk += e[j]*Wk[j*8+d]; sv += e[j]*Wv[j*8+d]; }
            ko[d] = sk; vo[d] = sv;
        }
    }
    for (int l = idx; l < LROWS; l += stride) {
        #pragma unroll
        for (int j = 0; j < 8; j++) g_xi[l*8+j] = x[l*8+j];
        #pragma unroll
        for (int c = 0; c < 4; c++) g_loc[l*4+c] = x[l*8+c];
    }
}

// ---------------- prep: mix enc_z with G -> g_eg (L x 64) --------------
__global__ void init_mix(const float* __restrict__ z, const float* __restrict__ enc,
                         const float* __restrict__ G) {
    __shared__ float sG[NSV*NSV];
    int b = blockIdx.x, i = threadIdx.x; // 64 threads
    for (int t = i; t < NSV*NSV; t += 64) sG[t] = G[t];
    __syncthreads();
    float v[NSV];
    if (i < 32) {
        #pragma unroll
        for (int m = 0; m < NSV; m++) v[m] = z[(b*NSV+m)*32 + i];
    } else {
        #pragma unroll
        for (int m = 0; m < NSV; m++) v[m] = enc[(b*NSV+m)*32 + (i-32)];
    }
    #pragma unroll
    for (int n = 0; n < NSV; n++) {
        float s = 0.f;
        #pragma unroll
        for (int m = 0; m < NSV; m++) s += sG[n*NSV+m]*v[m];
        g_eg[(b*NSV+n)*64 + i] = s;
    }
}

// ---------------- prep: h0/c0 = eg @ [W_h1|W_h2] + bias ----------------
__global__ void __launch_bounds__(256) init_gemm() {
    __shared__ float As[8][128];
    __shared__ float Bs[8][128];
    int tid = threadIdx.x;
    int bn = blockIdx.x, bm = blockIdx.y;
    int tx = tid & 15, ty = tid >> 4;
    float acc[8][8];
    #pragma unroll
    for (int i = 0; i < 8; i++)
        #pragma unroll
        for (int j = 0; j < 8; j++) acc[i][j] = 0.f;
    const float* A = g_eg + bm*128*64;
    int arow = tid >> 1, acol = (tid & 1)*4;
    int brow = tid >> 5, bcol = (tid & 31)*4;
    for (int k0 = 0; k0 < 64; k0 += 8) {
        float4 av = *(const float4*)(A + arow*64 + k0 + acol);
        As[acol+0][arow] = av.x; As[acol+1][arow] = av.y;
        As[acol+2][arow] = av.z; As[acol+3][arow] = av.w;
        float4 bv = *(const float4*)(g_Whc + (k0+brow)*512 + bn*128 + bcol);
        *(float4*)&Bs[brow][bcol] = bv;
        __syncthreads();
        #pragma unroll
        for (int kk = 0; kk < 8; kk++) {
            float a[8], bb[8];
            #pragma unroll
            for (int i = 0; i < 8; i++) a[i]  = As[kk][ty*8+i];
            #pragma unroll
            for (int j = 0; j < 8; j++) bb[j] = Bs[kk][tx*8+j];
            #pragma unroll
            for (int i = 0; i < 8; i++)
                #pragma unroll
                for (int j = 0; j < 8; j++) acc[i][j] += a[i]*bb[j];
        }
        __syncthreads();
    }
    #pragma unroll
    for (int i = 0; i < 8; i++) {
        int l = bm*128 + ty*8 + i;
        #pragma unroll
        for (int j = 0; j < 8; j++) {
            int col = bn*128 + tx*8 + j;
            float v = acc[i][j] + g_bhc[col];
            if (col < 256) g_h[l*HDIM + col] = v;
            else           g_c[l*HDIM + (col-256)] = v;
        }
    }
}

// ---------------- step: q + attention + inp build (warp per row) -------
// sWhdT stored TRANSPOSED [j][kk] -> conflict-free smem reads (fix for the
// measured 72.7% L1 bottleneck: old layout had 8-way bank conflicts).
__global__ void attn_kernel(const float* __restrict__ Whd, const float* __restrict__ bhd,
                            const float* __restrict__ Wq,  const float* __restrict__ bq,
                            const float* __restrict__ Wo,  const float* __restrict__ bo) {
    __shared__ float sWhdT[8*HDIM];
    __shared__ float sWq[64], sWo[64], sbq[8], sbo[8], sbhd[8];
    int tid = threadIdx.x;
    for (int i = tid; i < HDIM*8; i += 256) {
        int j = i >> 8, kk = i & 255;
        sWhdT[j*HDIM + kk] = Whd[kk*8 + j];
    }
    if (tid < 64) { sWq[tid] = Wq[tid]; sWo[tid] = Wo[tid]; }
    if (tid < 8)  { sbq[tid] = bq[tid]; sbo[tid] = bo[tid]; sbhd[tid] = bhd[tid]; }
    __syncthreads();
    int w = tid >> 5, lane = tid & 31;
    int l = blockIdx.x*8 + w;
    const float* crow = g_c + l*HDIM;
    float qa[8];
    #pragma unroll
    for (int j = 0; j < 8; j++) qa[j] = 0.f;
    for (int kk = lane; kk < HDIM; kk += 32) {
        float cv = crow[kk];
        #pragma unroll
        for (int j = 0; j < 8; j++) qa[j] += cv * sWhdT[j*HDIM + kk];
    }
    #pragma unroll
    for (int j = 0; j < 8; j++) qa[j] = wredsum(qa[j]) + sbhd[j];
    float qh[8];
    #pragma unroll
    for (int j = 0; j < 8; j++) {
        float s = sbq[j];
        #pragma unroll
        for (int d = 0; d < 8; d++) s += qa[d]*sWq[d*8+j];
        qh[j] = s;
    }
    float l0 = -1e30f, l1 = -1e30f;
    if (lane < ENCT) {
        const float4* kp = (const float4*)(g_kh + (l*ENCT + lane)*8);
        float4 k0 = kp[0], k1 = kp[1];
        l0 = 0.5f*(qh[0]*k0.x + qh[1]*k0.y + qh[2]*k0.z + qh[3]*k0.w);
        l1 = 0.5f*(qh[4]*k1.x + qh[5]*k1.y + qh[6]*k1.z + qh[7]*k1.w);
    }
    float m0 = wredmax(l0), m1 = wredmax(l1);
    float e0 = (lane < ENCT) ? __expf(l0 - m0) : 0.f;
    float e1 = (lane < ENCT) ? __expf(l1 - m1) : 0.f;
    float s0 = wredsum(e0), s1 = wredsum(e1);
    float w0 = e0 / s0, w1 = e1 / s1;
    float od[8];
    #pragma unroll
    for (int j = 0; j < 8; j++) od[j] = 0.f;
    if (lane < ENCT) {
        const float4* vp = (const float4*)(g_vh + (l*ENCT + lane)*8);
        float4 v0 = vp[0], v1 = vp[1];
        od[0] = w0*v0.x; od[1] = w0*v0.y; od[2] = w0*v0.z; od[3] = w0*v0.w;
        od[4] = w1*v1.x; od[5] = w1*v1.y; od[6] = w1*v1.z; od[7] = w1*v1.w;
    }
    #pragma unroll
    for (int j = 0; j < 8; j++) od[j] = wredsum(od[j]);
    float aval = 0.f;
    #pragma unroll
    for (int j = 0; j < 8; j++) {
        if (lane == j) {
            float s = sbo[j];
            #pragma unroll
            for (int d = 0; d < 8; d++) s += od[d]*sWo[d*8+j];
            aval = qa[j] + s;
        }
    }
    if (lane < 8) {
        g_inp[l*16 + lane]     = g_xi[l*8 + lane];
        g_inp[l*16 + 8 + lane] = aval;
    }
}

// ---------------- step: Geff-mix of [h | inp] -> bf16 split A (L x 272)
__global__ void mix_hg_kernel() {
    __shared__ float sG[NSV*NSV];
    int b = blockIdx.x, k = threadIdx.x; // 272 threads
    for (int i = threadIdx.x; i < NSV*NSV; i += blockDim.x) sG[i] = g_Geff[i];
    __syncthreads();
    float v[NSV];
    if (k < 256) {
        #pragma unroll
        for (int m = 0; m < NSV; m++) v[m] = g_h[(b*NSV+m)*HDIM + k];
    } else {
        int kk = k - 256;
        #pragma unroll
        for (int m = 0; m < NSV; m++) v[m] = g_inp[(b*NSV+m)*16 + kk];
    }
    #pragma unroll
    for (int n = 0; n < NSV; n++) {
        float s = 0.f;
        #pragma unroll
        for (int m = 0; m < NSV; m++) s += sG[n*NSV+m]*v[m];
        __nv_bfloat16 hi, lo; bf16_split(s, hi, lo);
        int o = (b*NSV+n)*K2 + k;
        g_Ahi[o] = hi; g_Alo[o] = lo;
    }
}

// ---------------- step: big GEMM (L x 272 @ 272 x 1024) + LSTM cell ----
__global__ void lstm_mma() {
    __shared__ __align__(16) __nv_bfloat16 sm[8*128*24]; // 48KB
    float acc[2][4][4];
    #pragma unroll
    for (int i = 0; i < 2; i++)
        #pragma unroll
        for (int j = 0; j < 4; j++)
            #pragma unroll
            for (int kq = 0; kq < 4; kq++) acc[i][j][kq] = 0.f;
    int bn = blockIdx.x, bm = blockIdx.y;
    uint32_t sbase = (uint32_t)__cvta_generic_to_shared(sm);
    mma_pipe<17>(sbase,
        (const char*)g_Ahi  + (size_t)bm*128*544,
        (const char*)g_Alo  + (size_t)bm*128*544,
        (const char*)g_WtLhi + (size_t)bn*128*544,
        (const char*)g_WtLlo + (size_t)bn*128*544,
        544, acc);

    const int tid = threadIdx.x;
    const int warp = tid >> 5, lane = tid & 31;
    const int wm = warp >> 2, wn = warp & 3, g = lane >> 2, t4 = lane & 3;
    const bool odd = (t4 & 1);
    #pragma unroll
    for (int mi = 0; mi < 2; mi++) {
        #pragma unroll
        for (int ni = 0; ni < 4; ni++) {
            int row = bm*128 + wm*32 + mi*16 + g;
            int cn  = bn*128 + wn*32 + ni*8 + t4*2;
            float b0 = g_blr[cn], b1 = g_blr[cn+1];
            float s0 = acc[mi][ni][0] + b0;
            float s1 = acc[mi][ni][1] + b1;
            float s2 = acc[mi][ni][2] + b0;
            float s3 = acc[mi][ni][3] + b1;
            float x0 = __shfl_xor_sync(0xffffffffu, odd ? s0 : s2, 1);
            float x1 = __shfl_xor_sync(0xffffffffu, odd ? s1 : s3, 1);
            int r  = row + (odd ? 8 : 0);
            float gi = odd ? x0 : s0;
            float gf = odd ? x1 : s1;
            float gg = odd ? s2 : x0;
            float go = odd ? s3 : x1;
            int u  = cn >> 2;
            int ci = r*HDIM + u;
            float cold = g_c[ci];
            float c2 = sigm(gf)*cold + sigm(gi)*tanhf(gg);
            float h2 = sigm(go)*tanhf(c2);
            g_c[ci] = c2;
            g_h[ci] = h2;
        }
    }
}

// ---------------- step: G-mix of relu(h2) -> bf16 split Y (L x 256) ----
__global__ void mix_yi(const float* __restrict__ G) {
    __shared__ float sG[NSV*NSV];
    int b = blockIdx.x, k = threadIdx.x; // 256 threads
    for (int i = threadIdx.x; i < NSV*NSV; i += blockDim.x) sG[i] = G[i];
    __syncthreads();
    float v[NSV];
    #pragma unroll
    for (int m = 0; m < NSV; m++) v[m] = fmaxf(g_h[(b*NSV+m)*HDIM + k], 0.f);
    #pragma unroll
    for (int n = 0; n < NSV; n++) {
        float s = 0.f;
        #pragma unroll
        for (int m = 0; m < NSV; m++) s += sG[n*NSV+m]*v[m];
        __nv_bfloat16 hi, lo; bf16_split(s, hi, lo);
        int o = (b*NSV+n)*HDIM + k;
        g_Yhi[o] = hi; g_Ylo[o] = lo;
    }
}

// ---------------- step: fc GEMM (L x 256 @ 256 x 128) + relu -----------
__global__ void fc_mma() {
    __shared__ __align__(16) __nv_bfloat16 sm[8*128*24]; // 48KB
    float acc[2][4][4];
    #pragma unroll
    for (int i = 0; i < 2; i++)
        #pragma unroll
        for (int j = 0; j < 4; j++)
            #pragma unroll
            for (int kq = 0; kq < 4; kq++) acc[i][j][kq] = 0.f;
    int bm = blockIdx.y;
    uint32_t sbase = (uint32_t)__cvta_generic_to_shared(sm);
    mma_pipe<16>(sbase,
        (const char*)g_Yhi + (size_t)bm*128*512,
        (const char*)g_Ylo + (size_t)bm*128*512,
        (const char*)g_WtFhi,
        (const char*)g_WtFlo,
        512, acc);

    const int tid = threadIdx.x;
    const int warp = tid >> 5, lane = tid & 31;
    const int wm = warp >> 2, wn = warp & 3, g = lane >> 2, t4 = lane & 3;
    #pragma unroll
    for (int mi = 0; mi < 2; mi++) {
        #pragma unroll
        for (int ni = 0; ni < 4; ni++) {
            int row = bm*128 + wm*32 + mi*16 + g;
            int col = wn*32 + ni*8 + t4*2;
            float b0 = g_bfc[col], b1 = g_bfc[col+1];
            g_y12[row*128 + col]       = fmaxf(acc[mi][ni][0] + b0, 0.f);
            g_y12[row*128 + col + 1]   = fmaxf(acc[mi][ni][1] + b1, 0.f);
            g_y12[(row+8)*128 + col]   = fmaxf(acc[mi][ni][2] + b0, 0.f);
            g_y12[(row+8)*128 + col+1] = fmaxf(acc[mi][ni][3] + b1, 0.f);
        }
    }
}

// ---------------- step: tail — per-batch block, y12 staged in smem -----
__global__ void __launch_bounds__(672) final_kernel(
    const float* __restrict__ G,
    const float* __restrict__ Wloc, const float* __restrict__ bloc,
    const float* __restrict__ Wlz,  const float* __restrict__ blz,
    float* __restrict__ out, int t) {
    __shared__ float sY[NSV][128];
    __shared__ float sG[NSV*NSV], sWl[64*3], sWz[64*4], sbl[3], sbz[4];
    int tid = threadIdx.x;
    int b = blockIdx.x;
    for (int i = tid; i < NSV*NSV; i += 672) sG[i] = G[i];
    if (tid < 64*3) sWl[tid] = Wloc[tid];
    if (tid < 64*4) sWz[tid] = Wlz[tid];
    if (tid < 3)    sbl[tid] = bloc[tid];
    if (tid < 4)    sbz[tid] = blz[tid];
    for (int i = tid; i < NSV*128; i += 672)
        sY[i >> 7][i & 127] = g_y12[b*NSV*128 + i];
    __syncthreads();
    int n = tid >> 5, lane = tid & 31;
    int l = b*NSV + n;
    float a0 = 0.f, a1 = 0.f, a2 = 0.f, a3 = 0.f;
    #pragma unroll
    for (int m = 0; m < NSV; m++) {
        float g = sG[n*NSV+m];
        a0 += g*sY[m][lane];      a1 += g*sY[m][lane+32];
        a2 += g*sY[m][lane+64];   a3 += g*sY[m][lane+96];
    }
    float p0 = a0*sWl[lane*3+0] + a1*sWl[(lane+32)*3+0];
    float p1 = a0*sWl[lane*3+1] + a1*sWl[(lane+32)*3+1];
    float p2 = a0*sWl[lane*3+2] + a1*sWl[(lane+32)*3+2];
    float z0 = a2*sWz[lane*4+0] + a3*sWz[(lane+32)*4+0];
    float z1 = a2*sWz[lane*4+1] + a3*sWz[(lane+32)*4+1];
    float z2 = a2*sWz[lane*4+2] + a3*sWz[(lane+32)*4+2];
    float z3 = a2*sWz[lane*4+3] + a3*sWz[(lane+32)*4+3];
    p0 = wredsum(p0) + sbl[0];
    p1 = wredsum(p1) + sbl[1];
    p2 = wredsum(p2) + sbl[2];
    z0 = (wredsum(z0) + sbz[0])*100.f;
    z1 = (wredsum(z1) + sbz[1])*100.f;
    z2 = (wredsum(z2) + sbz[2])*100.f;
    z3 = (wredsum(z3) + sbz[3])*100.f;
    float inv = rsqrtf(1.f + p0*p0 + p1*p1 + p2*p2);
    float qdw = inv, qdx = p0*inv, qdy = p1*inv, qdz = p2*inv;
    float4 qs = *(const float4*)(g_loc + l*4);
    float lw = qs.x*qdw - (qs.y*qdx + qs.z*qdy + qs.w*qdz);
    float vx = qs.x*qdx + qdw*qs.y + (qs.z*qdz - qs.w*qdy);
    float vy = qs.x*qdy + qdw*qs.z + (qs.w*qdx - qs.y*qdz);
    float vz = qs.x*qdz + qdw*qs.w + (qs.y*qdy - qs.z*qdx);
    if (lane == 0) {
        int base = ((b*PHN + t)*NSV + n)*4;
        out[base+0] = lw;  out[base+1] = vx;  out[base+2] = vy;  out[base+3] = vz;
        out[OFS + base+0] = qdw; out[OFS + base+1] = qdx;
        out[OFS + base+2] = qdy; out[OFS + base+3] = qdz;
        out[2*OFS + base+0] = z0; out[2*OFS + base+1] = z1;
        out[2*OFS + base+2] = z2; out[2*OFS + base+3] = z3;
        g_loc[l*4+0] = lw; g_loc[l*4+1] = vx; g_loc[l*4+2] = vy; g_loc[l*4+3] = vz;
        g_xi[l*8+0] = lw;  g_xi[l*8+1] = vx;  g_xi[l*8+2] = vy;  g_xi[l*8+3] = vz;
        g_xi[l*8+4] = qdw; g_xi[l*8+5] = qdx; g_xi[l*8+6] = qdy; g_xi[l*8+7] = qdz;
    }
}

// ---------------- launch ----------------
extern "C" void kernel_launch(void* const* d_in, const int* in_sizes, int n_in,
                              void* d_out, int out_size) {
    (void)in_sizes; (void)n_in; (void)out_size;
    const float* x      = (const float*)d_in[0];
    const float* enc    = (const float*)d_in[1];
    const float* fe     = (const float*)d_in[2];
    const float* z      = (const float*)d_in[3];
    const float* G      = (const float*)d_in[5];
    const float* G_add  = (const float*)d_in[6];
    const float* W_ih   = (const float*)d_in[7];
    const float* W_hh   = (const float*)d_in[8];
    const float* b_lstm = (const float*)d_in[9];
    const float* W_fc   = (const float*)d_in[10];
    const float* b_fc   = (const float*)d_in[11];
    const float* W_fc2  = (const float*)d_in[12];
    const float* b_fc2  = (const float*)d_in[13];
    const float* W_h1   = (const float*)d_in[14];
    const float* b_h1   = (const float*)d_in[15];
    const float* W_h2   = (const float*)d_in[16];
    const float* b_h2   = (const float*)d_in[17];
    const float* W_hd   = (const float*)d_in[18];
    const float* b_hd   = (const float*)d_in[19];
    const float* Wq     = (const float*)d_in[20];
    const float* bq     = (const float*)d_in[21];
    const float* Wk     = (const float*)d_in[22];
    const float* bk     = (const float*)d_in[23];
    const float* Wv     = (const float*)d_in[24];
    const float* bv     = (const float*)d_in[25];
    const float* Wo     = (const float*)d_in[26];
    const float* bo     = (const float*)d_in[27];
    const float* W_loc  = (const float*)d_in[28];
    const float* b_loc  = (const float*)d_in[29];
    const float* W_lz   = (const float*)d_in[30];
    const float* b_lz   = (const float*)d_in[31];
    float* out = (float*)d_out;

    prep_all<<<1024, 256>>>(W_hh, W_ih, b_lstm, G, G_add,
                            W_fc, b_fc, W_fc2, b_fc2, W_h1, W_h2, b_h1, b_h2,
                            fe, Wk, bk, Wv, bv, x);
    init_mix<<<BSZ, 64>>>(z, enc, G);
    init_gemm<<<dim3(4, 168), 256>>>();

    for (int t = 0; t < PHN; t++) {
        attn_kernel<<<LROWS/8, 256>>>(W_hd, b_hd, Wq, bq, Wo, bo);
        mix_hg_kernel<<<BSZ, 272>>>();
        lstm_mma<<<dim3(8, 168), 512>>>();
        mix_yi<<<BSZ, 256>>>(G);
        fc_mma<<<dim3(1, 168), 512>>>();
        final_kernel<<<BSZ, 672>>>(G, W_loc, b_loc, W_lz, b_lz, out, t);
    }
}